// round 16
// baseline (speedup 1.0000x reference)
#include <cuda_runtime.h>
#include <cuda_bf16.h>
#include <math.h>
#include <stdint.h>

#define N_NODES 50000
#define N_EDGES 800000
#define IN_DIM 256
#define HID 64
#define HEADS 4
#define NUM_GRAPHS 8
#define NEG_SLOPE 0.2f
#define SCAN_BLOCKS 49   // 49*1024 >= 50000

// ---------------- scratch (device globals; no allocation) ----------------
__device__ float g_xw1[(size_t)N_NODES * 256];   // x @ W1 (fp32, aggregation payload)
__device__ float g_xw2[(size_t)N_NODES * 64];    // h1 @ W2
__device__ uint32_t g_xhi [(size_t)N_NODES * 128];  // x as bf16x2 hi
__device__ uint32_t g_xlo [(size_t)N_NODES * 128];  // x as bf16x2 lo
__device__ uint32_t g_h1hi[(size_t)N_NODES * 128];  // h1 as bf16x2 hi
__device__ uint32_t g_h1lo[(size_t)N_NODES * 128];  // h1 as bf16x2 lo
__device__ float g_al1[N_NODES * 4];
__device__ float g_ar1[N_NODES * 4];
__device__ float g_al2[N_NODES];
__device__ float g_ar2[N_NODES];
__device__ int   g_deg[N_NODES];
__device__ int   g_rowptr[N_NODES + 1];
__device__ int   g_cursor[N_NODES];
__device__ int   g_csrc[N_EDGES];
__device__ int   g_bsum[SCAN_BLOCKS];
__device__ int   g_boff[SCAN_BLOCKS + 1];
__device__ float g_pool[NUM_GRAPHS * HID];
__device__ float g_cnt[NUM_GRAPHS];
// pre-split, pre-transposed weights: BT[n][k] (K-major), bf16 hi/lo
__device__ __nv_bfloat16 g_w1t_hi[256 * 256];
__device__ __nv_bfloat16 g_w1t_lo[256 * 256];
__device__ __nv_bfloat16 g_w2t_hi[64 * 256];
__device__ __nv_bfloat16 g_w2t_lo[64 * 256];

__device__ __forceinline__ float leakyf(float x) { return x > 0.f ? x : NEG_SLOPE * x; }
__device__ __forceinline__ float eluf(float x)   { return x > 0.f ? x : expm1f(x); }

// ---------------- mma.sync helpers (arch-neutral PTX, works at compute_103) ----
__device__ __forceinline__ uint32_t smem_u32(const void* p) {
    uint32_t a;
    asm("{ .reg .u64 t; cvta.to.shared.u64 t, %1; cvt.u32.u64 %0, t; }" : "=r"(a) : "l"(p));
    return a;
}
__device__ __forceinline__ void ldsm4(uint32_t* r, uint32_t addr) {
    asm volatile("ldmatrix.sync.aligned.m8n8.x4.shared.b16 {%0,%1,%2,%3}, [%4];"
                 : "=r"(r[0]), "=r"(r[1]), "=r"(r[2]), "=r"(r[3]) : "r"(addr));
}
__device__ __forceinline__ void mma16816(float* c, const uint32_t* a, uint32_t b0, uint32_t b1) {
    asm volatile("mma.sync.aligned.m16n8k16.row.col.f32.bf16.bf16.f32 "
                 "{%0,%1,%2,%3}, {%4,%5,%6,%7}, {%8,%9}, {%0,%1,%2,%3};"
                 : "+f"(c[0]), "+f"(c[1]), "+f"(c[2]), "+f"(c[3])
                 : "r"(a[0]), "r"(a[1]), "r"(a[2]), "r"(a[3]), "r"(b0), "r"(b1));
}

// ---------------- prep: weight transpose+split AND x -> bf16 hi/lo ----------------
__global__ void prep_kernel(const float* __restrict__ W1, const float* __restrict__ W2,
                            const float* __restrict__ x) {
    int i = blockIdx.x * blockDim.x + threadIdx.x;
    if (i < 256 * 256) {
        int n = i >> 8, k = i & 255;
        float v = W1[k * 256 + n];
        __nv_bfloat16 h = __float2bfloat16(v);
        g_w1t_hi[i] = h;
        g_w1t_lo[i] = __float2bfloat16(v - __bfloat162float(h));
    } else if (i < 256 * 256 + 64 * 256) {
        int j = i - 256 * 256;
        int n = j >> 8, k = j & 255;
        float v = W2[k * 64 + n];
        __nv_bfloat16 h = __float2bfloat16(v);
        g_w2t_hi[j] = h;
        g_w2t_lo[j] = __float2bfloat16(v - __bfloat162float(h));
    } else {
        int j = i - (256 * 256 + 64 * 256);
        if (j < N_NODES * 128) {
            float2 v = ((const float2*)x)[j];
            __nv_bfloat162 h, l;
            h.x = __float2bfloat16(v.x);
            h.y = __float2bfloat16(v.y);
            l.x = __float2bfloat16(v.x - __bfloat162float(h.x));
            l.y = __float2bfloat16(v.y - __bfloat162float(h.y));
            g_xhi[j] = *(uint32_t*)&h;
            g_xlo[j] = *(uint32_t*)&l;
        }
    }
}

// ---------------- zero / CSR build ----------------
__global__ void zero_kernel() {
    int i = blockIdx.x * blockDim.x + threadIdx.x;
    if (i < N_NODES) g_deg[i] = 0;
    if (i < N_NODES * 4) { g_al1[i] = 0.f; g_ar1[i] = 0.f; }
    if (i < N_NODES)     { g_al2[i] = 0.f; g_ar2[i] = 0.f; }
    if (i < NUM_GRAPHS * HID) g_pool[i] = 0.f;
    if (i < NUM_GRAPHS) g_cnt[i] = 0.f;
}

__global__ void hist_kernel(const int* __restrict__ dst) {
    int i = blockIdx.x * blockDim.x + threadIdx.x;
    if (i < N_EDGES) atomicAdd(&g_deg[dst[i]], 1);
}

__global__ void scan1_kernel() {
    __shared__ int sh[1024];
    int t = threadIdx.x;
    int gid = blockIdx.x * 1024 + t;
    int v = (gid < N_NODES) ? g_deg[gid] : 0;
    sh[t] = v;
    __syncthreads();
    for (int off = 1; off < 1024; off <<= 1) {
        int u = (t >= off) ? sh[t - off] : 0;
        __syncthreads();
        sh[t] += u;
        __syncthreads();
    }
    if (gid < N_NODES) g_rowptr[gid] = sh[t] - v;
    if (t == 1023) g_bsum[blockIdx.x] = sh[1023];
}

__global__ void scan2_kernel() {
    if (threadIdx.x == 0) {
        int run = 0;
        for (int b = 0; b < SCAN_BLOCKS; b++) {
            g_boff[b] = run;
            run += g_bsum[b];
        }
        g_boff[SCAN_BLOCKS] = run;
        g_rowptr[N_NODES] = run;
    }
}

__global__ void scan3_kernel() {
    int t = threadIdx.x;
    int gid = blockIdx.x * 1024 + t;
    if (gid < N_NODES) {
        int r = g_rowptr[gid] + g_boff[blockIdx.x];
        g_rowptr[gid] = r;
        g_cursor[gid] = r;
    }
}

__global__ void scatter_kernel(const int* __restrict__ src, const int* __restrict__ dst) {
    int i = blockIdx.x * blockDim.x + threadIdx.x;
    if (i < N_EDGES) {
        int d = dst[i];
        int pos = atomicAdd(&g_cursor[d], 1);
        g_csrc[pos] = src[i];
    }
}

// ---------------- split-bf16 tensor-core GEMM via mma.sync ----------------
// C[M,NTOT] = A[M,256] @ W[256,NTOT]; A pre-split bf16 hi/lo, W pre-transposed/split.
// CTA tile 128x64, BK=32, 8 warps (4 m x 2 n), warp tile 32x32.
// Fused: attention dots al/ar via quad-reduce + atomicAdd.
#define PAD 20   // u32 per smem row (16 used + 4 pad) -> conflict-free ldmatrix

template<int NTOT>
__global__ void __launch_bounds__(256, 2) gemm_mma_kernel(
    const float* __restrict__ asrc, const float* __restrict__ adst, int M)
{
    const uint32_t* Ahi = (NTOT == 256) ? g_xhi : g_h1hi;
    const uint32_t* Alo = (NTOT == 256) ? g_xlo : g_h1lo;
    const uint32_t* Bh32 = (const uint32_t*)((NTOT == 256) ? g_w1t_hi : g_w2t_hi);
    const uint32_t* Bl32 = (const uint32_t*)((NTOT == 256) ? g_w1t_lo : g_w2t_lo);
    float* C  = (NTOT == 256) ? g_xw1 : g_xw2;
    float* AL = (NTOT == 256) ? g_al1 : g_al2;
    float* AR = (NTOT == 256) ? g_ar1 : g_ar2;
    constexpr int H = NTOT / 64;        // heads in this layer

    __shared__ __align__(16) uint32_t sAhi[128 * PAD], sAlo[128 * PAD];
    __shared__ __align__(16) uint32_t sBhi[64 * PAD],  sBlo[64 * PAD];

    int tid = threadIdx.x, lane = tid & 31, wid = tid >> 5;
    int wm = wid >> 1, wn = wid & 1;
    int m0 = blockIdx.x * 128;
    int n0 = blockIdx.y * 64;
    int hd = blockIdx.y;                // head index (NTOT=256) or 0

    const float* as = asrc + hd * 64;   // a_src is [H, 64]
    const float* ad = adst + hd * 64;

    uint32_t aHiB = smem_u32(sAhi), aLoB = smem_u32(sAlo);
    uint32_t bHiB = smem_u32(sBhi), bLoB = smem_u32(sBlo);

    float acc[2][4][4];
#pragma unroll
    for (int am = 0; am < 2; am++)
#pragma unroll
        for (int bn = 0; bn < 4; bn++)
#pragma unroll
            for (int q = 0; q < 4; q++) acc[am][bn][q] = 0.f;

    uint32_t aoff[2];
#pragma unroll
    for (int am = 0; am < 2; am++) {
        int rowm = wm * 32 + am * 16 + (lane & 15);
        aoff[am] = (uint32_t)(rowm * PAD + (lane >> 4) * 4) * 4;
    }
    int rowbA = wn * 32 + ((lane >> 4) & 1) * 8 + (lane & 7);
    uint32_t boff[2];
#pragma unroll
    for (int bp = 0; bp < 2; bp++)
        boff[bp] = (uint32_t)((rowbA + bp * 16) * PAD + ((lane >> 3) & 1) * 4) * 4;

    int brf = tid >> 2;
    int bqf = tid & 3;

    for (int kc = 0; kc < 8; kc++) {       // K=256 in chunks of 32 (16 u32)
#pragma unroll
        for (int i = 0; i < 2; i++) {
            int v = tid + i * 256;
            int r = v >> 2, q = v & 3;
            int row = m0 + r; if (row >= M) row = M - 1;
            uint4 h = ((const uint4*)Ahi)[(size_t)row * 32 + kc * 4 + q];
            uint4 l = ((const uint4*)Alo)[(size_t)row * 32 + kc * 4 + q];
            *(uint4*)&sAhi[r * PAD + q * 4] = h;
            *(uint4*)&sAlo[r * PAD + q * 4] = l;
        }
        {
            uint4 h = ((const uint4*)Bh32)[(size_t)(n0 + brf) * 32 + kc * 4 + bqf];
            uint4 l = ((const uint4*)Bl32)[(size_t)(n0 + brf) * 32 + kc * 4 + bqf];
            *(uint4*)&sBhi[brf * PAD + bqf * 4] = h;
            *(uint4*)&sBlo[brf * PAD + bqf * 4] = l;
        }
        __syncthreads();

#pragma unroll
        for (int ks = 0; ks < 2; ks++) {
            uint32_t ahi[2][4], alo[2][4], bhi[2][4], blo[2][4];
            uint32_t kb = (uint32_t)(ks * 8 * 4);
#pragma unroll
            for (int am = 0; am < 2; am++) {
                ldsm4(ahi[am], aHiB + aoff[am] + kb);
                ldsm4(alo[am], aLoB + aoff[am] + kb);
            }
#pragma unroll
            for (int bp = 0; bp < 2; bp++) {
                ldsm4(bhi[bp], bHiB + boff[bp] + kb);
                ldsm4(blo[bp], bLoB + boff[bp] + kb);
            }
#pragma unroll
            for (int am = 0; am < 2; am++)
#pragma unroll
                for (int bp = 0; bp < 2; bp++)
#pragma unroll
                    for (int h = 0; h < 2; h++) {
                        float* c = acc[am][bp * 2 + h];
                        mma16816(c, ahi[am], bhi[bp][h * 2], bhi[bp][h * 2 + 1]);
                        mma16816(c, ahi[am], blo[bp][h * 2], blo[bp][h * 2 + 1]);
                        mma16816(c, alo[am], bhi[bp][h * 2], bhi[bp][h * 2 + 1]);
                    }
        }
        __syncthreads();
    }

    // ---- epilogue: write C + fused attention dots ----
    int gr = lane >> 2;
    int gc = (lane & 3) * 2;
#pragma unroll
    for (int am = 0; am < 2; am++) {
        int row0 = m0 + wm * 32 + am * 16 + gr;
        float pal0 = 0.f, par0 = 0.f, pal1 = 0.f, par1 = 0.f;
#pragma unroll
        for (int bn = 0; bn < 4; bn++) {
            int c = wn * 32 + bn * 8 + gc;
            float s0 = as[c], s1 = as[c + 1];
            float d0 = ad[c], d1 = ad[c + 1];
            pal0 += acc[am][bn][0] * s0 + acc[am][bn][1] * s1;
            par0 += acc[am][bn][0] * d0 + acc[am][bn][1] * d1;
            pal1 += acc[am][bn][2] * s0 + acc[am][bn][3] * s1;
            par1 += acc[am][bn][2] * d0 + acc[am][bn][3] * d1;

            int col = n0 + c;
            if (row0 < M)
                *(float2*)(C + (size_t)row0 * NTOT + col) = make_float2(acc[am][bn][0], acc[am][bn][1]);
            if (row0 + 8 < M)
                *(float2*)(C + (size_t)(row0 + 8) * NTOT + col) = make_float2(acc[am][bn][2], acc[am][bn][3]);
        }
#pragma unroll
        for (int off = 1; off <= 2; off <<= 1) {
            pal0 += __shfl_xor_sync(0xffffffffu, pal0, off);
            par0 += __shfl_xor_sync(0xffffffffu, par0, off);
            pal1 += __shfl_xor_sync(0xffffffffu, pal1, off);
            par1 += __shfl_xor_sync(0xffffffffu, par1, off);
        }
        if ((lane & 3) == 0) {
            if (row0 < M) {
                atomicAdd(&AL[row0 * H + hd], pal0);
                atomicAdd(&AR[row0 * H + hd], par0);
            }
            if (row0 + 8 < M) {
                atomicAdd(&AL[(row0 + 8) * H + hd], pal1);
                atomicAdd(&AR[(row0 + 8) * H + hd], par1);
            }
        }
    }
}

// ---- online-softmax accumulate step for layer 1 (8 channels in a0,a1) ----
#define ACC1(EV, X0, X1) do { \
    float e = leakyf((EV) + arh); \
    float mn = fmaxf(m, e); \
    float r  = __expf(m - mn); \
    float wt = __expf(e - mn); \
    s = s * r + wt; \
    m = mn; \
    a0.x = a0.x * r + wt * (X0).x;  a0.y = a0.y * r + wt * (X0).y; \
    a0.z = a0.z * r + wt * (X0).z;  a0.w = a0.w * r + wt * (X0).w; \
    a1.x = a1.x * r + wt * (X1).x;  a1.y = a1.y * r + wt * (X1).y; \
    a1.z = a1.z * r + wt * (X1).z;  a1.w = a1.w * r + wt * (X1).w; \
} while (0)

// ---------------- layer-1 aggregation: warp per dst node, unroll-4 MLP ----------------
__global__ void aggregate1_kernel(const float* __restrict__ bias) {
    int w = (blockIdx.x * blockDim.x + threadIdx.x) >> 5;
    if (w >= N_NODES) return;
    int lane = threadIdx.x & 31;
    int hd = lane >> 3;

    float arh = g_ar1[w * 4 + hd];
    float m = leakyf(g_al1[w * 4 + hd] + arh);
    float s = 1.f;

    const float4* xself = (const float4*)(g_xw1 + (size_t)w * 256) + lane * 2;
    float4 a0 = xself[0], a1 = xself[1];

    int p0 = g_rowptr[w], p1 = g_rowptr[w + 1];
    int p = p0;
    for (; p + 4 <= p1; p += 4) {
        // batch all loads of the group first (MLP ~ 8 payload lines in flight)
        int s0 = g_csrc[p + 0], s1 = g_csrc[p + 1], s2 = g_csrc[p + 2], s3 = g_csrc[p + 3];
        float e0 = g_al1[s0 * 4 + hd];
        float e1 = g_al1[s1 * 4 + hd];
        float e2 = g_al1[s2 * 4 + hd];
        float e3 = g_al1[s3 * 4 + hd];
        const float4* q0 = (const float4*)(g_xw1 + (size_t)s0 * 256) + lane * 2;
        const float4* q1 = (const float4*)(g_xw1 + (size_t)s1 * 256) + lane * 2;
        const float4* q2 = (const float4*)(g_xw1 + (size_t)s2 * 256) + lane * 2;
        const float4* q3 = (const float4*)(g_xw1 + (size_t)s3 * 256) + lane * 2;
        float4 x00 = q0[0], x01 = q0[1];
        float4 x10 = q1[0], x11 = q1[1];
        float4 x20 = q2[0], x21 = q2[1];
        float4 x30 = q3[0], x31 = q3[1];
        ACC1(e0, x00, x01);
        ACC1(e1, x10, x11);
        ACC1(e2, x20, x21);
        ACC1(e3, x30, x31);
    }
    for (; p < p1; p++) {
        int sp = g_csrc[p];
        float ev = g_al1[sp * 4 + hd];
        const float4* q = (const float4*)(g_xw1 + (size_t)sp * 256) + lane * 2;
        float4 x0 = q[0], x1 = q[1];
        ACC1(ev, x0, x1);
    }

    float inv = 1.f / s;
    int cb = lane * 8;
    float o[8];
    o[0] = eluf(a0.x * inv + bias[cb + 0]);
    o[1] = eluf(a0.y * inv + bias[cb + 1]);
    o[2] = eluf(a0.z * inv + bias[cb + 2]);
    o[3] = eluf(a0.w * inv + bias[cb + 3]);
    o[4] = eluf(a1.x * inv + bias[cb + 4]);
    o[5] = eluf(a1.y * inv + bias[cb + 5]);
    o[6] = eluf(a1.z * inv + bias[cb + 6]);
    o[7] = eluf(a1.w * inv + bias[cb + 7]);
    __nv_bfloat162 hh[4], ll[4];
#pragma unroll
    for (int j = 0; j < 4; j++) {
        hh[j].x = __float2bfloat16(o[2 * j]);
        hh[j].y = __float2bfloat16(o[2 * j + 1]);
        ll[j].x = __float2bfloat16(o[2 * j]     - __bfloat162float(hh[j].x));
        ll[j].y = __float2bfloat16(o[2 * j + 1] - __bfloat162float(hh[j].y));
    }
    ((uint4*)g_h1hi)[(size_t)w * 32 + lane] = *(uint4*)hh;
    ((uint4*)g_h1lo)[(size_t)w * 32 + lane] = *(uint4*)ll;
}

#define ACC2(EV, X) do { \
    float e = leakyf((EV) + arh); \
    float mn = fmaxf(m, e); \
    float r  = __expf(m - mn); \
    float wt = __expf(e - mn); \
    s = s * r + wt; \
    m = mn; \
    a.x = a.x * r + wt * (X).x; \
    a.y = a.y * r + wt * (X).y; \
} while (0)

// ---------------- layer-2 aggregation + pooling atomics (unroll-4) ----------------
__global__ void aggregate2_kernel(const float* __restrict__ bias, const int* __restrict__ batch,
                                  float* __restrict__ out) {
    int w = (blockIdx.x * blockDim.x + threadIdx.x) >> 5;
    if (w >= N_NODES) return;
    int lane = threadIdx.x & 31;

    float arh = g_ar2[w];
    float m = leakyf(g_al2[w] + arh);
    float s = 1.f;
    float2 a = ((const float2*)(g_xw2 + (size_t)w * 64))[lane];

    int p0 = g_rowptr[w], p1 = g_rowptr[w + 1];
    int p = p0;
    for (; p + 4 <= p1; p += 4) {
        int s0 = g_csrc[p + 0], s1 = g_csrc[p + 1], s2 = g_csrc[p + 2], s3 = g_csrc[p + 3];
        float e0 = g_al2[s0], e1 = g_al2[s1], e2 = g_al2[s2], e3 = g_al2[s3];
        float2 x0 = ((const float2*)(g_xw2 + (size_t)s0 * 64))[lane];
        float2 x1 = ((const float2*)(g_xw2 + (size_t)s1 * 64))[lane];
        float2 x2 = ((const float2*)(g_xw2 + (size_t)s2 * 64))[lane];
        float2 x3 = ((const float2*)(g_xw2 + (size_t)s3 * 64))[lane];
        ACC2(e0, x0);
        ACC2(e1, x1);
        ACC2(e2, x2);
        ACC2(e3, x3);
    }
    for (; p < p1; p++) {
        int sp = g_csrc[p];
        float ev = g_al2[sp];
        float2 x = ((const float2*)(g_xw2 + (size_t)sp * 64))[lane];
        ACC2(ev, x);
    }

    float inv = 1.f / s;
    float v0 = eluf(a.x * inv + bias[lane * 2 + 0]);
    float v1 = eluf(a.y * inv + bias[lane * 2 + 1]);
    ((float2*)(out + (size_t)w * 64))[lane] = make_float2(v0, v1);

    int b = batch[w];
    atomicAdd(&g_pool[b * 64 + lane * 2 + 0], v0);
    atomicAdd(&g_pool[b * 64 + lane * 2 + 1], v1);
    if (lane == 0) atomicAdd(&g_cnt[b], 1.f);
}

// ---------------- final FC ----------------
__global__ void fc_kernel(const float* __restrict__ fcW, const float* __restrict__ fcb,
                          float* __restrict__ out) {
    int t = threadIdx.x;
    if (t >= NUM_GRAPHS * 2) return;
    int g = t >> 1, k = t & 1;
    float c = fmaxf(g_cnt[g], 1.f);
    float sum = 0.f;
    for (int ch = 0; ch < HID; ch++) sum += g_pool[g * HID + ch] * fcW[ch * 2 + k];
    out[t] = sum / c + fcb[k];
}

// ---------------- launch ----------------
extern "C" void kernel_launch(void* const* d_in, const int* in_sizes, int n_in,
                              void* d_out, int out_size) {
    const float* x      = (const float*)d_in[0];
    const int*   ei     = (const int*)  d_in[1];
    const int*   batch  = (const int*)  d_in[2];
    const float* W1     = (const float*)d_in[3];
    const float* a_src1 = (const float*)d_in[4];
    const float* a_dst1 = (const float*)d_in[5];
    const float* b1     = (const float*)d_in[6];
    const float* W2     = (const float*)d_in[7];
    const float* a_src2 = (const float*)d_in[8];
    const float* a_dst2 = (const float*)d_in[9];
    const float* b2     = (const float*)d_in[10];
    const float* fcW    = (const float*)d_in[11];
    const float* fcb    = (const float*)d_in[12];
    float* out = (float*)d_out;

    const int* src = ei;
    const int* dst = ei + N_EDGES;

    const int NBLK = (N_NODES + 127) / 128;   // 391

    // Launch index 3 = ncu capture slot -> hist_kernel this round.
    const int PREP_ITEMS = 256 * 256 + 64 * 256 + N_NODES * 128;
    prep_kernel<<<(PREP_ITEMS + 255) / 256, 256>>>(W1, W2, x);          // 0
    zero_kernel<<<(N_NODES * 4 + 255) / 256, 256>>>();                  // 1

    dim3 grid1(NBLK, 4);
    gemm_mma_kernel<256><<<grid1, 256>>>(a_src1, a_dst1, N_NODES);      // 2

    hist_kernel<<<(N_EDGES + 255) / 256, 256>>>(dst);                   // 3 <- profiled
    scan1_kernel<<<SCAN_BLOCKS, 1024>>>();                              // 4
    scan2_kernel<<<1, 32>>>();                                          // 5
    scan3_kernel<<<SCAN_BLOCKS, 1024>>>();                              // 6
    scatter_kernel<<<(N_EDGES + 255) / 256, 256>>>(src, dst);           // 7

    aggregate1_kernel<<<(N_NODES + 7) / 8, 256>>>(b1);                  // 8

    dim3 grid2(NBLK, 1);
    gemm_mma_kernel<64><<<grid2, 256>>>(a_src2, a_dst2, N_NODES);       // 9
    aggregate2_kernel<<<(N_NODES + 7) / 8, 256>>>(b2, batch, out);      // 10

    fc_kernel<<<1, 32>>>(fcW, fcb, out + (size_t)N_NODES * HID);        // 11
}

// round 17
// speedup vs baseline: 1.0297x; 1.0297x over previous
#include <cuda_runtime.h>
#include <cuda_bf16.h>
#include <math.h>
#include <stdint.h>

#define N_NODES 50000
#define N_EDGES 800000
#define IN_DIM 256
#define HID 64
#define HEADS 4
#define NUM_GRAPHS 8
#define NEG_SLOPE 0.2f
#define SCAN_BLOCKS 49   // 49*1024 >= 50000

// ---------------- scratch (device globals; no allocation) ----------------
__device__ float g_xw1[(size_t)N_NODES * 256];      // x @ W1 (fp32, aggregation payload)
__device__ float g_xw2[(size_t)N_NODES * 64];       // h1 @ W2
__device__ uint32_t g_h1hi[(size_t)N_NODES * 128];  // h1 as bf16x2 hi (gemm2 operand)
__device__ uint32_t g_h1lo[(size_t)N_NODES * 128];  // h1 as bf16x2 lo
__device__ float g_al1[N_NODES * 4];
__device__ float g_ar1[N_NODES * 4];
__device__ float g_al2[N_NODES];
__device__ float g_ar2[N_NODES];
__device__ int   g_deg[N_NODES];
__device__ int   g_rowptr[N_NODES + 1];
__device__ int   g_cursor[N_NODES];
__device__ int   g_csrc[N_EDGES];
__device__ int   g_bsum[SCAN_BLOCKS];
__device__ int   g_boff[SCAN_BLOCKS + 1];
__device__ float g_pool[NUM_GRAPHS * HID];
__device__ float g_cnt[NUM_GRAPHS];
// pre-split, pre-transposed weights: BT[n][k] (K-major), bf16 hi/lo
__device__ __nv_bfloat16 g_w1t_hi[256 * 256];
__device__ __nv_bfloat16 g_w1t_lo[256 * 256];
__device__ __nv_bfloat16 g_w2t_hi[64 * 256];
__device__ __nv_bfloat16 g_w2t_lo[64 * 256];

__device__ __forceinline__ float leakyf(float x) { return x > 0.f ? x : NEG_SLOPE * x; }
__device__ __forceinline__ float eluf(float x)   { return x > 0.f ? x : expm1f(x); }

// ---------------- mma.sync helpers (arch-neutral PTX, works at compute_103) ----
__device__ __forceinline__ uint32_t smem_u32(const void* p) {
    uint32_t a;
    asm("{ .reg .u64 t; cvta.to.shared.u64 t, %1; cvt.u32.u64 %0, t; }" : "=r"(a) : "l"(p));
    return a;
}
__device__ __forceinline__ void ldsm4(uint32_t* r, uint32_t addr) {
    asm volatile("ldmatrix.sync.aligned.m8n8.x4.shared.b16 {%0,%1,%2,%3}, [%4];"
                 : "=r"(r[0]), "=r"(r[1]), "=r"(r[2]), "=r"(r[3]) : "r"(addr));
}
__device__ __forceinline__ void mma16816(float* c, const uint32_t* a, uint32_t b0, uint32_t b1) {
    asm volatile("mma.sync.aligned.m16n8k16.row.col.f32.bf16.bf16.f32 "
                 "{%0,%1,%2,%3}, {%4,%5,%6,%7}, {%8,%9}, {%0,%1,%2,%3};"
                 : "+f"(c[0]), "+f"(c[1]), "+f"(c[2]), "+f"(c[3])
                 : "r"(a[0]), "r"(a[1]), "r"(a[2]), "r"(a[3]), "r"(b0), "r"(b1));
}

// ---------------- prep: weight transpose + bf16 split (weights only) ----------------
__global__ void prep_kernel(const float* __restrict__ W1, const float* __restrict__ W2) {
    int i = blockIdx.x * blockDim.x + threadIdx.x;
    if (i < 256 * 256) {
        int n = i >> 8, k = i & 255;
        float v = W1[k * 256 + n];
        __nv_bfloat16 h = __float2bfloat16(v);
        g_w1t_hi[i] = h;
        g_w1t_lo[i] = __float2bfloat16(v - __bfloat162float(h));
    } else if (i < 256 * 256 + 64 * 256) {
        int j = i - 256 * 256;
        int n = j >> 8, k = j & 255;
        float v = W2[k * 64 + n];
        __nv_bfloat16 h = __float2bfloat16(v);
        g_w2t_hi[j] = h;
        g_w2t_lo[j] = __float2bfloat16(v - __bfloat162float(h));
    }
}

// ---------------- zero / CSR build ----------------
__global__ void zero_kernel() {
    int i = blockIdx.x * blockDim.x + threadIdx.x;
    if (i < N_NODES) g_deg[i] = 0;
    if (i < N_NODES * 4) { g_al1[i] = 0.f; g_ar1[i] = 0.f; }
    if (i < N_NODES)     { g_al2[i] = 0.f; g_ar2[i] = 0.f; }
    if (i < NUM_GRAPHS * HID) g_pool[i] = 0.f;
    if (i < NUM_GRAPHS) g_cnt[i] = 0.f;
}

__global__ void hist_kernel(const int* __restrict__ dst) {
    int i = blockIdx.x * blockDim.x + threadIdx.x;
    if (i < N_EDGES) atomicAdd(&g_deg[dst[i]], 1);
}

__global__ void scan1_kernel() {
    __shared__ int sh[1024];
    int t = threadIdx.x;
    int gid = blockIdx.x * 1024 + t;
    int v = (gid < N_NODES) ? g_deg[gid] : 0;
    sh[t] = v;
    __syncthreads();
    for (int off = 1; off < 1024; off <<= 1) {
        int u = (t >= off) ? sh[t - off] : 0;
        __syncthreads();
        sh[t] += u;
        __syncthreads();
    }
    if (gid < N_NODES) g_rowptr[gid] = sh[t] - v;
    if (t == 1023) g_bsum[blockIdx.x] = sh[1023];
}

__global__ void scan2_kernel() {
    if (threadIdx.x == 0) {
        int run = 0;
        for (int b = 0; b < SCAN_BLOCKS; b++) {
            g_boff[b] = run;
            run += g_bsum[b];
        }
        g_boff[SCAN_BLOCKS] = run;
        g_rowptr[N_NODES] = run;
    }
}

__global__ void scan3_kernel() {
    int t = threadIdx.x;
    int gid = blockIdx.x * 1024 + t;
    if (gid < N_NODES) {
        int r = g_rowptr[gid] + g_boff[blockIdx.x];
        g_rowptr[gid] = r;
        g_cursor[gid] = r;
    }
}

__global__ void scatter_kernel(const int* __restrict__ src, const int* __restrict__ dst) {
    int i = blockIdx.x * blockDim.x + threadIdx.x;
    if (i < N_EDGES) {
        int d = dst[i];
        int pos = atomicAdd(&g_cursor[d], 1);
        g_csrc[pos] = src[i];
    }
}

// ---------------- split-bf16 tensor-core GEMM via mma.sync ----------------
// C[M,NTOT] = A[M,256] @ W[256,NTOT].
// NTOT=256: A = x (fp32, converted inline). NTOT=64: A = h1 pre-split bf16 hi/lo.
// CTA tile 128x64, BK=32, 8 warps (4 m x 2 n), warp tile 32x32.
// Fused: attention dots al/ar via quad-reduce + atomicAdd.
#define PAD 20   // u32 per smem row (16 used + 4 pad) -> conflict-free ldmatrix

template<int NTOT>
__global__ void __launch_bounds__(256, 2) gemm_mma_kernel(
    const float* __restrict__ Aext,
    const float* __restrict__ asrc, const float* __restrict__ adst, int M)
{
    const uint32_t* Bh32 = (const uint32_t*)((NTOT == 256) ? g_w1t_hi : g_w2t_hi);
    const uint32_t* Bl32 = (const uint32_t*)((NTOT == 256) ? g_w1t_lo : g_w2t_lo);
    float* C  = (NTOT == 256) ? g_xw1 : g_xw2;
    float* AL = (NTOT == 256) ? g_al1 : g_al2;
    float* AR = (NTOT == 256) ? g_ar1 : g_ar2;
    constexpr int H = NTOT / 64;        // heads in this layer

    __shared__ __align__(16) uint32_t sAhi[128 * PAD], sAlo[128 * PAD];
    __shared__ __align__(16) uint32_t sBhi[64 * PAD],  sBlo[64 * PAD];

    int tid = threadIdx.x, lane = tid & 31, wid = tid >> 5;
    int wm = wid >> 1, wn = wid & 1;
    int m0 = blockIdx.x * 128;
    int n0 = blockIdx.y * 64;
    int hd = blockIdx.y;                // head index (NTOT=256) or 0

    const float* as = asrc + hd * 64;   // a_src is [H, 64]
    const float* ad = adst + hd * 64;

    uint32_t aHiB = smem_u32(sAhi), aLoB = smem_u32(sAlo);
    uint32_t bHiB = smem_u32(sBhi), bLoB = smem_u32(sBlo);

    float acc[2][4][4];
#pragma unroll
    for (int am = 0; am < 2; am++)
#pragma unroll
        for (int bn = 0; bn < 4; bn++)
#pragma unroll
            for (int q = 0; q < 4; q++) acc[am][bn][q] = 0.f;

    uint32_t aoff[2];
#pragma unroll
    for (int am = 0; am < 2; am++) {
        int rowm = wm * 32 + am * 16 + (lane & 15);
        aoff[am] = (uint32_t)(rowm * PAD + (lane >> 4) * 4) * 4;
    }
    int rowbA = wn * 32 + ((lane >> 4) & 1) * 8 + (lane & 7);
    uint32_t boff[2];
#pragma unroll
    for (int bp = 0; bp < 2; bp++)
        boff[bp] = (uint32_t)((rowbA + bp * 16) * PAD + ((lane >> 3) & 1) * 4) * 4;

    int brf = tid >> 2;
    int bqf = tid & 3;

    for (int kc = 0; kc < 8; kc++) {       // K=256 in chunks of 32
        if (NTOT == 256) {
            // A = fp32 x, convert inline to bf16 hi/lo
#pragma unroll
            for (int i = 0; i < 4; i++) {
                int v = tid + i * 256;
                int r = v >> 3, c4 = v & 7;
                int row = m0 + r; if (row >= M) row = M - 1;
                float4 f = *(const float4*)(Aext + (size_t)row * 256 + kc * 32 + c4 * 4);
                __nv_bfloat162 h0, h1, l0, l1;
                h0.x = __float2bfloat16(f.x); h0.y = __float2bfloat16(f.y);
                h1.x = __float2bfloat16(f.z); h1.y = __float2bfloat16(f.w);
                l0.x = __float2bfloat16(f.x - __bfloat162float(h0.x));
                l0.y = __float2bfloat16(f.y - __bfloat162float(h0.y));
                l1.x = __float2bfloat16(f.z - __bfloat162float(h1.x));
                l1.y = __float2bfloat16(f.w - __bfloat162float(h1.y));
                sAhi[r * PAD + c4 * 2 + 0] = *(uint32_t*)&h0;
                sAhi[r * PAD + c4 * 2 + 1] = *(uint32_t*)&h1;
                sAlo[r * PAD + c4 * 2 + 0] = *(uint32_t*)&l0;
                sAlo[r * PAD + c4 * 2 + 1] = *(uint32_t*)&l1;
            }
        } else {
            // A = h1 pre-split bf16 hi/lo, pure uint4 copies
#pragma unroll
            for (int i = 0; i < 2; i++) {
                int v = tid + i * 256;
                int r = v >> 2, q = v & 3;
                int row = m0 + r; if (row >= M) row = M - 1;
                uint4 h = ((const uint4*)g_h1hi)[(size_t)row * 32 + kc * 4 + q];
                uint4 l = ((const uint4*)g_h1lo)[(size_t)row * 32 + kc * 4 + q];
                *(uint4*)&sAhi[r * PAD + q * 4] = h;
                *(uint4*)&sAlo[r * PAD + q * 4] = l;
            }
        }
        {
            uint4 h = ((const uint4*)Bh32)[(size_t)(n0 + brf) * 32 + kc * 4 + bqf];
            uint4 l = ((const uint4*)Bl32)[(size_t)(n0 + brf) * 32 + kc * 4 + bqf];
            *(uint4*)&sBhi[brf * PAD + bqf * 4] = h;
            *(uint4*)&sBlo[brf * PAD + bqf * 4] = l;
        }
        __syncthreads();

#pragma unroll
        for (int ks = 0; ks < 2; ks++) {
            uint32_t ahi[2][4], alo[2][4], bhi[2][4], blo[2][4];
            uint32_t kb = (uint32_t)(ks * 8 * 4);
#pragma unroll
            for (int am = 0; am < 2; am++) {
                ldsm4(ahi[am], aHiB + aoff[am] + kb);
                ldsm4(alo[am], aLoB + aoff[am] + kb);
            }
#pragma unroll
            for (int bp = 0; bp < 2; bp++) {
                ldsm4(bhi[bp], bHiB + boff[bp] + kb);
                ldsm4(blo[bp], bLoB + boff[bp] + kb);
            }
#pragma unroll
            for (int am = 0; am < 2; am++)
#pragma unroll
                for (int bp = 0; bp < 2; bp++)
#pragma unroll
                    for (int h = 0; h < 2; h++) {
                        float* c = acc[am][bp * 2 + h];
                        mma16816(c, ahi[am], bhi[bp][h * 2], bhi[bp][h * 2 + 1]);
                        mma16816(c, ahi[am], blo[bp][h * 2], blo[bp][h * 2 + 1]);
                        mma16816(c, alo[am], bhi[bp][h * 2], bhi[bp][h * 2 + 1]);
                    }
        }
        __syncthreads();
    }

    // ---- epilogue: write C + fused attention dots ----
    int gr = lane >> 2;
    int gc = (lane & 3) * 2;
#pragma unroll
    for (int am = 0; am < 2; am++) {
        int row0 = m0 + wm * 32 + am * 16 + gr;
        float pal0 = 0.f, par0 = 0.f, pal1 = 0.f, par1 = 0.f;
#pragma unroll
        for (int bn = 0; bn < 4; bn++) {
            int c = wn * 32 + bn * 8 + gc;
            float s0 = as[c], s1 = as[c + 1];
            float d0 = ad[c], d1 = ad[c + 1];
            pal0 += acc[am][bn][0] * s0 + acc[am][bn][1] * s1;
            par0 += acc[am][bn][0] * d0 + acc[am][bn][1] * d1;
            pal1 += acc[am][bn][2] * s0 + acc[am][bn][3] * s1;
            par1 += acc[am][bn][2] * d0 + acc[am][bn][3] * d1;

            int col = n0 + c;
            if (row0 < M)
                *(float2*)(C + (size_t)row0 * NTOT + col) = make_float2(acc[am][bn][0], acc[am][bn][1]);
            if (row0 + 8 < M)
                *(float2*)(C + (size_t)(row0 + 8) * NTOT + col) = make_float2(acc[am][bn][2], acc[am][bn][3]);
        }
#pragma unroll
        for (int off = 1; off <= 2; off <<= 1) {
            pal0 += __shfl_xor_sync(0xffffffffu, pal0, off);
            par0 += __shfl_xor_sync(0xffffffffu, par0, off);
            pal1 += __shfl_xor_sync(0xffffffffu, pal1, off);
            par1 += __shfl_xor_sync(0xffffffffu, par1, off);
        }
        if ((lane & 3) == 0) {
            if (row0 < M) {
                atomicAdd(&AL[row0 * H + hd], pal0);
                atomicAdd(&AR[row0 * H + hd], par0);
            }
            if (row0 + 8 < M) {
                atomicAdd(&AL[(row0 + 8) * H + hd], pal1);
                atomicAdd(&AR[(row0 + 8) * H + hd], par1);
            }
        }
    }
}

// ---- online-softmax step: one head, 4 channels ----
#define STEP4(M_, S_, A_, EV, ARH, X) do { \
    float e_ = leakyf((EV) + (ARH)); \
    float mn_ = fmaxf(M_, e_); \
    float r_  = __expf(M_ - mn_); \
    float wt_ = __expf(e_ - mn_); \
    S_ = S_ * r_ + wt_; \
    M_ = mn_; \
    A_.x = A_.x * r_ + wt_ * (X).x; \
    A_.y = A_.y * r_ + wt_ * (X).y; \
    A_.z = A_.z * r_ + wt_ * (X).z; \
    A_.w = A_.w * r_ + wt_ * (X).w; \
} while (0)

// ---------------- layer-1 aggregation: warp per dst node ----------------
// Coalesced payload: lane loads contiguous float4 at lane*16B from each 512B
// half-row (each LDG.128 = fully-packed 512B). Lane owns 4 channels in head
// (lane>>4) and 4 channels in head 2+(lane>>4). Per-head math unchanged.
__global__ void aggregate1_kernel(const float* __restrict__ bias) {
    int w = (blockIdx.x * blockDim.x + threadIdx.x) >> 5;
    if (w >= N_NODES) return;
    int lane = threadIdx.x & 31;
    int h0 = lane >> 4;        // head of first half-row channels
    int h1i = 2 + h0;          // head of second half-row channels

    float arh0 = g_ar1[w * 4 + h0];
    float arh1 = g_ar1[w * 4 + h1i];
    float m0 = leakyf(g_al1[w * 4 + h0] + arh0);
    float m1 = leakyf(g_al1[w * 4 + h1i] + arh1);
    float s0 = 1.f, s1 = 1.f;

    const float* base = g_xw1 + (size_t)w * 256;
    float4 A0 = ((const float4*)base)[lane];           // channels lane*4 .. +3
    float4 A1 = ((const float4*)(base + 128))[lane];   // channels 128+lane*4 ..

    int p0 = g_rowptr[w], p1 = g_rowptr[w + 1];
    int p = p0;
    for (; p + 2 <= p1; p += 2) {
        int sA = g_csrc[p], sB = g_csrc[p + 1];
        float eA0 = g_al1[sA * 4 + h0], eA1 = g_al1[sA * 4 + h1i];
        float eB0 = g_al1[sB * 4 + h0], eB1 = g_al1[sB * 4 + h1i];
        const float* bA = g_xw1 + (size_t)sA * 256;
        const float* bB = g_xw1 + (size_t)sB * 256;
        float4 xA0 = ((const float4*)bA)[lane];
        float4 xA1 = ((const float4*)(bA + 128))[lane];
        float4 xB0 = ((const float4*)bB)[lane];
        float4 xB1 = ((const float4*)(bB + 128))[lane];
        STEP4(m0, s0, A0, eA0, arh0, xA0);
        STEP4(m1, s1, A1, eA1, arh1, xA1);
        STEP4(m0, s0, A0, eB0, arh0, xB0);
        STEP4(m1, s1, A1, eB1, arh1, xB1);
    }
    for (; p < p1; p++) {
        int sp = g_csrc[p];
        float e0 = g_al1[sp * 4 + h0], e1 = g_al1[sp * 4 + h1i];
        const float* bp_ = g_xw1 + (size_t)sp * 256;
        float4 x0 = ((const float4*)bp_)[lane];
        float4 x1 = ((const float4*)(bp_ + 128))[lane];
        STEP4(m0, s0, A0, e0, arh0, x0);
        STEP4(m1, s1, A1, e1, arh1, x1);
    }

    float i0 = 1.f / s0, i1 = 1.f / s1;
    int cb0 = lane * 4, cb1 = 128 + lane * 4;
    float o0[4], o1[4];
    o0[0] = eluf(A0.x * i0 + bias[cb0 + 0]);
    o0[1] = eluf(A0.y * i0 + bias[cb0 + 1]);
    o0[2] = eluf(A0.z * i0 + bias[cb0 + 2]);
    o0[3] = eluf(A0.w * i0 + bias[cb0 + 3]);
    o1[0] = eluf(A1.x * i1 + bias[cb1 + 0]);
    o1[1] = eluf(A1.y * i1 + bias[cb1 + 1]);
    o1[2] = eluf(A1.z * i1 + bias[cb1 + 2]);
    o1[3] = eluf(A1.w * i1 + bias[cb1 + 3]);

    // h1 split-store: channels lane*4..+3 -> u32 idx lane*2, lane*2+1 (uint2 @ lane)
    __nv_bfloat162 h, l;
    uint2 hi0, lo0, hi1, lo1;
    h.x = __float2bfloat16(o0[0]); h.y = __float2bfloat16(o0[1]);
    l.x = __float2bfloat16(o0[0] - __bfloat162float(h.x));
    l.y = __float2bfloat16(o0[1] - __bfloat162float(h.y));
    hi0.x = *(uint32_t*)&h; lo0.x = *(uint32_t*)&l;
    h.x = __float2bfloat16(o0[2]); h.y = __float2bfloat16(o0[3]);
    l.x = __float2bfloat16(o0[2] - __bfloat162float(h.x));
    l.y = __float2bfloat16(o0[3] - __bfloat162float(h.y));
    hi0.y = *(uint32_t*)&h; lo0.y = *(uint32_t*)&l;
    h.x = __float2bfloat16(o1[0]); h.y = __float2bfloat16(o1[1]);
    l.x = __float2bfloat16(o1[0] - __bfloat162float(h.x));
    l.y = __float2bfloat16(o1[1] - __bfloat162float(h.y));
    hi1.x = *(uint32_t*)&h; lo1.x = *(uint32_t*)&l;
    h.x = __float2bfloat16(o1[2]); h.y = __float2bfloat16(o1[3]);
    l.x = __float2bfloat16(o1[2] - __bfloat162float(h.x));
    l.y = __float2bfloat16(o1[3] - __bfloat162float(h.y));
    hi1.y = *(uint32_t*)&h; lo1.y = *(uint32_t*)&l;

    ((uint2*)g_h1hi)[(size_t)w * 64 + lane]      = hi0;
    ((uint2*)g_h1hi)[(size_t)w * 64 + 32 + lane] = hi1;
    ((uint2*)g_h1lo)[(size_t)w * 64 + lane]      = lo0;
    ((uint2*)g_h1lo)[(size_t)w * 64 + 32 + lane] = lo1;
}

#define ACC2(EV, X) do { \
    float e = leakyf((EV) + arh); \
    float mn = fmaxf(m, e); \
    float r  = __expf(m - mn); \
    float wt = __expf(e - mn); \
    s = s * r + wt; \
    m = mn; \
    a.x = a.x * r + wt * (X).x; \
    a.y = a.y * r + wt * (X).y; \
} while (0)

// ---------------- layer-2 aggregation + pooling atomics ----------------
__global__ void aggregate2_kernel(const float* __restrict__ bias, const int* __restrict__ batch,
                                  float* __restrict__ out) {
    int w = (blockIdx.x * blockDim.x + threadIdx.x) >> 5;
    if (w >= N_NODES) return;
    int lane = threadIdx.x & 31;

    float arh = g_ar2[w];
    float m = leakyf(g_al2[w] + arh);
    float s = 1.f;
    float2 a = ((const float2*)(g_xw2 + (size_t)w * 64))[lane];

    int p0 = g_rowptr[w], p1 = g_rowptr[w + 1];
    int p = p0;
    for (; p + 4 <= p1; p += 4) {
        int s0 = g_csrc[p + 0], s1 = g_csrc[p + 1], s2 = g_csrc[p + 2], s3 = g_csrc[p + 3];
        float e0 = g_al2[s0], e1 = g_al2[s1], e2 = g_al2[s2], e3 = g_al2[s3];
        float2 x0 = ((const float2*)(g_xw2 + (size_t)s0 * 64))[lane];
        float2 x1 = ((const float2*)(g_xw2 + (size_t)s1 * 64))[lane];
        float2 x2 = ((const float2*)(g_xw2 + (size_t)s2 * 64))[lane];
        float2 x3 = ((const float2*)(g_xw2 + (size_t)s3 * 64))[lane];
        ACC2(e0, x0);
        ACC2(e1, x1);
        ACC2(e2, x2);
        ACC2(e3, x3);
    }
    for (; p < p1; p++) {
        int sp = g_csrc[p];
        float ev = g_al2[sp];
        float2 x = ((const float2*)(g_xw2 + (size_t)sp * 64))[lane];
        ACC2(ev, x);
    }

    float inv = 1.f / s;
    float v0 = eluf(a.x * inv + bias[lane * 2 + 0]);
    float v1 = eluf(a.y * inv + bias[lane * 2 + 1]);
    ((float2*)(out + (size_t)w * 64))[lane] = make_float2(v0, v1);

    int b = batch[w];
    atomicAdd(&g_pool[b * 64 + lane * 2 + 0], v0);
    atomicAdd(&g_pool[b * 64 + lane * 2 + 1], v1);
    if (lane == 0) atomicAdd(&g_cnt[b], 1.f);
}

// ---------------- final FC ----------------
__global__ void fc_kernel(const float* __restrict__ fcW, const float* __restrict__ fcb,
                          float* __restrict__ out) {
    int t = threadIdx.x;
    if (t >= NUM_GRAPHS * 2) return;
    int g = t >> 1, k = t & 1;
    float c = fmaxf(g_cnt[g], 1.f);
    float sum = 0.f;
    for (int ch = 0; ch < HID; ch++) sum += g_pool[g * HID + ch] * fcW[ch * 2 + k];
    out[t] = sum / c + fcb[k];
}

// ---------------- launch ----------------
extern "C" void kernel_launch(void* const* d_in, const int* in_sizes, int n_in,
                              void* d_out, int out_size) {
    const float* x      = (const float*)d_in[0];
    const int*   ei     = (const int*)  d_in[1];
    const int*   batch  = (const int*)  d_in[2];
    const float* W1     = (const float*)d_in[3];
    const float* a_src1 = (const float*)d_in[4];
    const float* a_dst1 = (const float*)d_in[5];
    const float* b1     = (const float*)d_in[6];
    const float* W2     = (const float*)d_in[7];
    const float* a_src2 = (const float*)d_in[8];
    const float* a_dst2 = (const float*)d_in[9];
    const float* b2     = (const float*)d_in[10];
    const float* fcW    = (const float*)d_in[11];
    const float* fcb    = (const float*)d_in[12];
    float* out = (float*)d_out;

    const int* src = ei;
    const int* dst = ei + N_EDGES;

    const int NBLK = (N_NODES + 127) / 128;   // 391

    // Launch index 3 = ncu capture slot -> gemm1 (inline-convert variant).
    const int PREP_ITEMS = 256 * 256 + 64 * 256;
    prep_kernel<<<(PREP_ITEMS + 255) / 256, 256>>>(W1, W2);             // 0
    zero_kernel<<<(N_NODES * 4 + 255) / 256, 256>>>();                  // 1
    hist_kernel<<<(N_EDGES + 255) / 256, 256>>>(dst);                   // 2

    dim3 grid1(NBLK, 4);
    gemm_mma_kernel<256><<<grid1, 256>>>(x, a_src1, a_dst1, N_NODES);   // 3 <- profiled

    scan1_kernel<<<SCAN_BLOCKS, 1024>>>();                              // 4
    scan2_kernel<<<1, 32>>>();                                          // 5
    scan3_kernel<<<SCAN_BLOCKS, 1024>>>();                              // 6
    scatter_kernel<<<(N_EDGES + 255) / 256, 256>>>(src, dst);           // 7

    aggregate1_kernel<<<(N_NODES + 7) / 8, 256>>>(b1);                  // 8

    dim3 grid2(NBLK, 1);
    gemm_mma_kernel<64><<<grid2, 256>>>(nullptr, a_src2, a_dst2, N_NODES); // 9
    aggregate2_kernel<<<(N_NODES + 7) / 8, 256>>>(b2, batch, out);      // 10

    fc_kernel<<<1, 32>>>(fcW, fcb, out + (size_t)N_NODES * HID);        // 11
}